// round 12
// baseline (speedup 1.0000x reference)
#include <cuda_runtime.h>
#include <cuda_fp16.h>
#include <cstdint>
#include <cstddef>

#define TPB     512
#define NW      16            // warps; each owns 8 hidden cols x 4 gates (N=32)
#define MB      16            // batch rows per CTA
#define TSTEPS  512
#define ISZ     5
#define TI      (TSTEPS*ISZ)
#define HID     128
#define KTOT    144           // 128 h + 5 x + 1 bias + 10 zero pad
#define KCH     9             // K chunks of 16
#define WSTR    152           // halves per row (304B stride: ldmatrix conflict-free)

#define B_BYTES   (512*WSTR*2)        // B staging (resident, read once into regs)
#define A_BYTES   (MB*WSTR*2)         // 4864 per buffer
#define SMEM_B    0
#define SMEM_A0   B_BYTES
#define SMEM_A1   (SMEM_A0 + A_BYTES)
#define SMEM_TOTAL (SMEM_A1 + A_BYTES)

__device__ __forceinline__ uint32_t smem_u32(const void* p) {
    uint32_t a;
    asm("{ .reg .u64 t; cvta.to.shared.u64 t, %1; cvt.u32.u64 %0, t; }" : "=r"(a) : "l"(p));
    return a;
}
#define LDSM4(r0, r1, r2, r3, addr) \
    asm volatile("ldmatrix.sync.aligned.m8n8.x4.shared.b16 {%0,%1,%2,%3}, [%4];" \
        : "=r"(r0), "=r"(r1), "=r"(r2), "=r"(r3) : "r"(addr))
#define MMA16816(d, a0, a1, a2, a3, b0, b1) \
    asm volatile("mma.sync.aligned.m16n8k16.row.col.f32.f16.f16.f32 " \
        "{%0,%1,%2,%3}, {%4,%5,%6,%7}, {%8,%9}, {%0,%1,%2,%3};" \
        : "+f"((d)[0]), "+f"((d)[1]), "+f"((d)[2]), "+f"((d)[3]) \
        : "r"(a0), "r"(a1), "r"(a2), "r"(a3), "r"(b0), "r"(b1))

// packed fp16x2 tanh: 2 values per MUFU op (inputs/outputs converted f32<->f16)
__device__ __forceinline__ float2 tanh2(float a, float b) {
    __half2 h = __floats2half2_rn(a, b);
    uint32_t u = *reinterpret_cast<uint32_t*>(&h);
    asm("tanh.approx.f16x2 %0, %0;" : "+r"(u));
    h = *reinterpret_cast<__half2*>(&u);
    return __half22float2(h);
}
__device__ __forceinline__ float2 sig2(float a, float b) {
    float2 t = tanh2(0.5f * a, 0.5f * b);
    return make_float2(fmaf(0.5f, t.x, 0.5f), fmaf(0.5f, t.y, 0.5f));
}

__global__ void __launch_bounds__(TPB, 1)
lstm_hmma(const float* __restrict__ x,     const float* __restrict__ W_ih,
          const float* __restrict__ W_hh,  const float* __restrict__ b_ih,
          const float* __restrict__ b_hh,  const float* __restrict__ W_lin,
          const float* __restrict__ b_lin, float* __restrict__ out)
{
    extern __shared__ char smem[];
    const uint32_t sb = smem_u32(smem);
    const int tid = threadIdx.x;
    const int w = tid >> 5, l = tid & 31;
    const int q = l >> 2, m = l & 3;     // C rows q,q+8; cols 2m,2m+1 (within tile)
    const int b0 = blockIdx.x * MB;
    const int j0 = 8 * w + 2 * m;        // this lane's hidden col pair

    // ---- stage B = W, fp16 [ni][k], ni = w*32 + g*8 + jj  (gate = n8 tile) ----
    for (int e = tid; e < 512 * KTOT; e += TPB) {
        int ni = e / KTOT, k = e - ni * KTOT;
        int wb = ni >> 5, rem = ni & 31;
        int g = rem >> 3, jj = rem & 7;
        int nsrc = g * HID + wb * 8 + jj;
        float v = 0.f;
        if (k < HID)        v = W_hh[nsrc * HID + k];
        else if (k < 133)   v = W_ih[nsrc * ISZ + (k - HID)];
        else if (k == 133)  v = b_ih[nsrc] + b_hh[nsrc];
        *reinterpret_cast<__half*>(smem + SMEM_B + (size_t)(ni * WSTR + k) * 2) = __float2half(v);
    }
    __syncthreads();

    // ---- hoist this warp's B slice into registers: 9 chunks x 8 regs ----
    // Bq[ch][0,1]=gate i, [2,3]=gate f, [4,5]=gate g, [6,7]=gate o
    uint32_t Bq[KCH][8];
    {
        const uint32_t bl = sb + SMEM_B +
            (uint32_t)(((32 * w + ((l >> 4) & 1) * 8 + (l & 7)) * WSTR + ((l >> 3) & 1) * 8) * 2);
        #pragma unroll
        for (int ch = 0; ch < KCH; ch++) {
            LDSM4(Bq[ch][0], Bq[ch][1], Bq[ch][2], Bq[ch][3], bl + ch * 32);
            LDSM4(Bq[ch][4], Bq[ch][5], Bq[ch][6], Bq[ch][7],
                  bl + (uint32_t)(16 * WSTR * 2) + ch * 32);
        }
    }
    __syncthreads();

    // ---- init A buffers: zero, bias col (both), x(t=0) into buffer 0 ----
    for (int i = tid; i < 2 * A_BYTES / 4; i += TPB)
        reinterpret_cast<uint32_t*>(smem + SMEM_A0)[i] = 0u;
    __syncthreads();
    if (tid < MB) {
        *reinterpret_cast<__half*>(smem + SMEM_A0 + (tid * WSTR + 133) * 2) = __float2half(1.f);
        *reinterpret_cast<__half*>(smem + SMEM_A1 + (tid * WSTR + 133) * 2) = __float2half(1.f);
    }
    if (tid < MB * ISZ) {
        int r = tid / ISZ, i = tid - r * ISZ;
        *reinterpret_cast<__half*>(smem + SMEM_A0 + (r * WSTR + HID + i) * 2) =
            __float2half(x[(size_t)(b0 + r) * TI + i]);
    }

    // A x4 lane address: [rows0-7 klo, rows8-15 klo, rows0-7 khi, rows8-15 khi]
    const uint32_t a_lane0 = sb + SMEM_A0 +
        (uint32_t)(((((l >> 3) & 1) * 8 + (l & 7)) * WSTR + ((l >> 4) & 1) * 8) * 2);
    const uint32_t a_lane1 = a_lane0 + A_BYTES;

    float c_st[4];
    c_st[0] = c_st[1] = c_st[2] = c_st[3] = 0.f;

    for (int t = 0; t < TSTEPS; t++) {
        __syncthreads();                       // A[read buffer] fully written
        const uint32_t Ard = (t & 1) ? a_lane1 : a_lane0;

        // x(t+1) prefetch (LDG early; stored into write buffer later)
        float xv = 0.f; int xr = 0, xi = 0;
        const bool dox = (tid < MB * ISZ) && (t + 1 < TSTEPS);
        if (dox) {
            xr = tid / ISZ; xi = tid - xr * ISZ;
            xv = x[(size_t)(b0 + xr) * TI + (size_t)(t + 1) * ISZ + xi];
        }

        float Ci[4], Cf[4], Cg[4], Co[4];
        #pragma unroll
        for (int u = 0; u < 4; u++) { Ci[u] = 0.f; Cf[u] = 0.f; Cg[u] = 0.f; Co[u] = 0.f; }

        #pragma unroll
        for (int ch = 0; ch < KCH; ch++) {
            uint32_t a0, a1, a2, a3;
            LDSM4(a0, a1, a2, a3, Ard + ch * 32);
            MMA16816(Ci, a0, a1, a2, a3, Bq[ch][0], Bq[ch][1]);
            MMA16816(Cf, a0, a1, a2, a3, Bq[ch][2], Bq[ch][3]);
            MMA16816(Cg, a0, a1, a2, a3, Bq[ch][4], Bq[ch][5]);
            MMA16816(Co, a0, a1, a2, a3, Bq[ch][6], Bq[ch][7]);
        }

        __half* Aw = reinterpret_cast<__half*>(
            smem + SMEM_A0 + ((t & 1) ^ 1) * A_BYTES);

        // ---- activations: packed f16x2 tanh (10 MUFU/thread), c stays fp32 ----
        float2 si01 = sig2(Ci[0], Ci[1]), si23 = sig2(Ci[2], Ci[3]);
        float2 sf01 = sig2(Cf[0], Cf[1]), sf23 = sig2(Cf[2], Cf[3]);
        float2 tg01 = tanh2(Cg[0], Cg[1]), tg23 = tanh2(Cg[2], Cg[3]);
        float cc0 = fmaf(sf01.x, c_st[0], si01.x * tg01.x);
        float cc1 = fmaf(sf01.y, c_st[1], si01.y * tg01.y);
        float cc2 = fmaf(sf23.x, c_st[2], si23.x * tg23.x);
        float cc3 = fmaf(sf23.y, c_st[3], si23.y * tg23.y);
        c_st[0] = cc0; c_st[1] = cc1; c_st[2] = cc2; c_st[3] = cc3;
        float2 so01 = sig2(Co[0], Co[1]), so23 = sig2(Co[2], Co[3]);
        float2 tc01 = tanh2(cc0, cc1),   tc23 = tanh2(cc2, cc3);
        float h0 = so01.x * tc01.x, h1 = so01.y * tc01.y;
        float h2 = so23.x * tc23.x, h3 = so23.y * tc23.y;

        // h writeback: units 0,1 -> (row q); units 2,3 -> (row q+8)
        *reinterpret_cast<__half2*>(&Aw[q * WSTR + j0])       = __floats2half2_rn(h0, h1);
        *reinterpret_cast<__half2*>(&Aw[(q + 8) * WSTR + j0]) = __floats2half2_rn(h2, h3);

        if (dox) Aw[xr * WSTR + HID + xi] = __float2half_rn(xv);
    }

    __syncthreads();
    // ---- epilogue: final h is in buffer 0 (t=511 wrote rb^1 = 0) ----
    if (tid < 128) {
        const int row = tid >> 3, seg = tid & 7;
        const __half* Hf = reinterpret_cast<const __half*>(smem + SMEM_A0);
        float s = 0.f;
        #pragma unroll
        for (int jj = 0; jj < 16; jj++) {
            int j = seg * 16 + jj;
            s += __half2float(Hf[row * WSTR + j]) * W_lin[j];
        }
        s += __shfl_xor_sync(0xffffffffu, s, 4);
        s += __shfl_xor_sync(0xffffffffu, s, 2);
        s += __shfl_xor_sync(0xffffffffu, s, 1);
        if (seg == 0) out[b0 + row] = s + b_lin[0];
    }
}

extern "C" void kernel_launch(void* const* d_in, const int* in_sizes, int n_in,
                              void* d_out, int out_size) {
    const float* x     = (const float*)d_in[0];
    const float* W_ih  = (const float*)d_in[1];
    const float* W_hh  = (const float*)d_in[2];
    const float* b_ih  = (const float*)d_in[3];
    const float* b_hh  = (const float*)d_in[4];
    const float* W_lin = (const float*)d_in[5];
    const float* b_lin = (const float*)d_in[6];
    float* out = (float*)d_out;

    int B    = in_sizes[0] / TI;   // 2048
    int nCTA = B / MB;             // 128 CTAs, one wave

    cudaFuncSetAttribute(lstm_hmma,
                         cudaFuncAttributeMaxDynamicSharedMemorySize, SMEM_TOTAL);
    lstm_hmma<<<nCTA, TPB, SMEM_TOTAL>>>(x, W_ih, W_hh, b_ih, b_hh,
                                         W_lin, b_lin, out);
}